// round 9
// baseline (speedup 1.0000x reference)
#include <cuda_runtime.h>
#include <cstdint>

#define NE       64
#define ND       1024
#define NTOK     65536
#define TILE_M   128
#define KC       16              // fp32 K per pipeline stage
#define NCHUNK   (ND / KC)       // 64
#define NTHREADS 128

// ---- static smem layout (float indices) ----
// A stage: [2][KC][132]  (128 tokens + 4 pad)     = 16896 B
// W stage: [2][KC][132]  (64 experts duplicated -> 128 floats + 4 pad) = 16896 B
// bias: 64 f32.  Epilogue slog[128][64] overlays A+W region (32 KB).
#define ROWF        132
#define A_BASE      0
#define A_STAGEF    (KC * ROWF)            // 2112 floats per stage
#define W_BASE      (2 * A_STAGEF)         // float index 4224
#define W_STAGEF    (KC * ROWF)
#define BG_BASE     (W_BASE + 2 * W_STAGEF)  // 8448
#define SMEM_FLOATS (BG_BASE + NE)

__device__ __forceinline__ void fma2(unsigned long long& acc,
                                     unsigned long long a,
                                     unsigned long long b) {
    asm("fma.rn.f32x2 %0, %1, %2, %0;" : "+l"(acc) : "l"(a), "l"(b));
}
__device__ __forceinline__ unsigned long long packdup(float f) {
    unsigned long long d;
    const uint32_t u = __float_as_uint(f);
    asm("mov.b64 %0, {%1, %1};" : "=l"(d) : "r"(u));
    return d;
}

__global__ __launch_bounds__(NTHREADS, 4)
void router_ffma2_kernel(const float* __restrict__ tokens,
                         const int* __restrict__ t_arr,
                         const float* __restrict__ Wg,
                         const float* __restrict__ bg,
                         float* __restrict__ out)
{
    __shared__ __align__(16) float smem[SMEM_FLOATS];

    const int tid = threadIdx.x;
    const int bm  = blockIdx.x * TILE_M;
    const int tg  = tid & 15;          // token group: {4tg..4tg+3, 64+4tg..+3}
    const int eg  = tid >> 4;          // expert group: 8eg..8eg+7

    if (tid < NE) smem[BG_BASE + tid] = bg[tid];

    // acc[tp][e]: tp 0,1 = token pairs (4tg,4tg+1),(4tg+2,4tg+3);
    //             tp 2,3 = same +64.  e = expert 8eg+e.  f32x2 packed.
    unsigned long long acc[4][8];
#pragma unroll
    for (int tp = 0; tp < 4; tp++)
#pragma unroll
        for (int e = 0; e < 8; e++) acc[tp][e] = 0ull;

    float4 la[4], lw[2];

#define LOAD(k0)                                                               \
    {                                                                          \
        _Pragma("unroll")                                                      \
        for (int i = 0; i < 4; i++) {                                          \
            const int j = tid + NTHREADS * i;                                  \
            const int m = j >> 2, q = j & 3;                                   \
            la[i] = *reinterpret_cast<const float4*>(                          \
                tokens + (size_t)(bm + m) * ND + (k0) + 4 * q);                \
        }                                                                      \
        _Pragma("unroll")                                                      \
        for (int i = 0; i < 2; i++) {                                          \
            const int j = tid + NTHREADS * i;                                  \
            const int e = j >> 2, q = j & 3;                                   \
            lw[i] = *reinterpret_cast<const float4*>(                          \
                Wg + (size_t)e * ND + (k0) + 4 * q);                           \
        }                                                                      \
    }

// A: transpose scalar stores to padded [k][132] (<=2-way conflicts).
// W: store each value as a duplicated u64 pair at float idx k*132 + 2e.
#define STORE(buf)                                                             \
    {                                                                          \
        float* sa = smem + A_BASE + (buf) * A_STAGEF;                          \
        float* sw = smem + W_BASE + (buf) * W_STAGEF;                          \
        _Pragma("unroll")                                                      \
        for (int i = 0; i < 4; i++) {                                          \
            const int j = tid + NTHREADS * i;                                  \
            const int m = j >> 2, q = j & 3;                                   \
            const float v[4] = {la[i].x, la[i].y, la[i].z, la[i].w};           \
            _Pragma("unroll")                                                  \
            for (int r = 0; r < 4; r++)                                        \
                sa[(4 * q + r) * ROWF + m] = v[r];                             \
        }                                                                      \
        _Pragma("unroll")                                                      \
        for (int i = 0; i < 2; i++) {                                          \
            const int j = tid + NTHREADS * i;                                  \
            const int e = j >> 2, q = j & 3;                                   \
            const float v[4] = {lw[i].x, lw[i].y, lw[i].z, lw[i].w};           \
            _Pragma("unroll")                                                  \
            for (int r = 0; r < 4; r++)                                        \
                *reinterpret_cast<unsigned long long*>(                        \
                    sw + (4 * q + r) * ROWF + 2 * e) = packdup(v[r]);          \
        }                                                                      \
    }

    LOAD(0);
    STORE(0);
    __syncthreads();

    // hoisted compute-side base pointers (per-k offsets become immediates)
    const float* saT = smem + A_BASE + 4 * tg;
    const float* swT = smem + W_BASE + 16 * eg;

    for (int ch = 0; ch < NCHUNK; ch++) {
        const int buf = ch & 1;
        if (ch + 1 < NCHUNK) LOAD((ch + 1) * KC);

        const float* sa = saT + buf * A_STAGEF;
        const float* sw = swT + buf * W_STAGEF;

#pragma unroll
        for (int k = 0; k < KC; k++) {
            const ulonglong2 A0 =
                *reinterpret_cast<const ulonglong2*>(sa + k * ROWF);
            const ulonglong2 A1 =
                *reinterpret_cast<const ulonglong2*>(sa + k * ROWF + 64);
            const ulonglong2 W0 =
                *reinterpret_cast<const ulonglong2*>(sw + k * ROWF);
            const ulonglong2 W1 =
                *reinterpret_cast<const ulonglong2*>(sw + k * ROWF + 4);
            const ulonglong2 W2 =
                *reinterpret_cast<const ulonglong2*>(sw + k * ROWF + 8);
            const ulonglong2 W3 =
                *reinterpret_cast<const ulonglong2*>(sw + k * ROWF + 12);

            const unsigned long long a64[4] = {A0.x, A0.y, A1.x, A1.y};
            const unsigned long long wd[8] = {W0.x, W0.y, W1.x, W1.y,
                                              W2.x, W2.y, W3.x, W3.y};
#pragma unroll
            for (int tp = 0; tp < 4; tp++)
#pragma unroll
                for (int e = 0; e < 8; e++) fma2(acc[tp][e], a64[tp], wd[e]);
        }

        if (ch + 1 < NCHUNK) STORE(buf ^ 1);   // disjoint buffer: safe pre-sync
        __syncthreads();
    }

    // ---- scatter acc -> swizzled logits overlay ----
    float* slog = smem;   // [128][64], col e ^ (m&31)
#pragma unroll
    for (int tp = 0; tp < 4; tp++) {
        const int m0 = ((tp & 1) ? 4 * tg + 2 : 4 * tg) + ((tp & 2) ? 64 : 0);
        const int m1 = m0 + 1;
#pragma unroll
        for (int e = 0; e < 8; e++) {
            const int ex = 8 * eg + e;
            slog[m0 * 64 + (ex ^ (m0 & 31))] =
                __uint_as_float((uint32_t)acc[tp][e]);
            slog[m1 * 64 + (ex ^ (m1 & 31))] =
                __uint_as_float((uint32_t)(acc[tp][e] >> 32));
        }
    }
    __syncthreads();

    // ---- per-token epilogue (identical math to the passing kernels) ----
    {
        const int m = tid;
        const int gtok = bm + m;
        const float cap = 0.5f + 1.1f * ((float)t_arr[gtok >> 12] / 1000.0f);
        const int msw = m & 31;
        const float* row = slog + m * 64;
        const float* sbg = smem + BG_BASE;

        float p[NE];
#pragma unroll
        for (int e = 0; e < NE; e++) p[e] = row[e ^ msw] + sbg[e];

        float mx = -3.402823466e38f;
#pragma unroll 8
        for (int e = 0; e < NE; e++) mx = fmaxf(mx, p[e]);
        float s = 0.0f;
#pragma unroll 4
        for (int e = 0; e < NE; e++) { const float v = expf(p[e] - mx); s += v; p[e] = v; }
        const float inv = 1.0f / s;

        float summin = 0.0f, sumex = 0.0f;
#pragma unroll 8
        for (int e = 0; e < NE; e++) {
            const float q = 0.85f * (p[e] * inv) + (0.15f / 64.0f);
            p[e] = q;
            const float cc = fminf(q, cap);
            summin += cc;
            sumex += q - cc;
        }
        const float hs = fmaxf(64.0f * cap - summin, 1e-8f);
        const float scale = sumex / hs;

        float v1 = -1.0f, v2 = -1.0f;
        int i1 = 0, i2 = 0;
#pragma unroll 8
        for (int e = 0; e < NE; e++) {
            const float cc = fminf(p[e], cap);
            const float f = cc + scale * (cap - cc);
            if (f > v1)      { v2 = v1; i2 = i1; v1 = f; i1 = e; }
            else if (f > v2) { v2 = f; i2 = e; }
        }

        float* orow = out + (size_t)gtok * NE;
        const float4 z = make_float4(0.f, 0.f, 0.f, 0.f);
#pragma unroll
        for (int u = 0; u < 16; u++) reinterpret_cast<float4*>(orow)[u] = z;
        orow[i1] = v1;
        orow[i2] = v2;
    }
}

extern "C" void kernel_launch(void* const* d_in, const int* in_sizes, int n_in,
                              void* d_out, int out_size)
{
    const float* tokens = (const float*)d_in[0];   // (16, 4096, 1024) f32
    const int*   t_arr  = (const int*)d_in[1];     // (16,) i32
    const float* Wg     = (const float*)d_in[2];   // (64, 1024) f32
    const float* bg     = (const float*)d_in[3];   // (64,) f32
    float*       out    = (float*)d_out;           // (16, 4096, 64) f32

    router_ffma2_kernel<<<NTOK / TILE_M, NTHREADS>>>(tokens, t_arr, Wg, bg, out);
}

// round 11
// speedup vs baseline: 1.1293x; 1.1293x over previous
#include <cuda_runtime.h>
#include <cstdint>

#define NE       64
#define ND       1024
#define NTOK     65536
#define TILE_M   128
#define KC       16              // fp32 K per pipeline stage
#define NCHUNK   (ND / KC)       // 64
#define NTHREADS 128

// ---- static smem layout (float indices), padded-linear (no XOR) ----
// A stage: [2][KC][132]  (128 tokens + 4 pad)
// W stage: [2][KC][68]   (64 experts + 4 pad)
// epilogue overlay slog[128][64] = 8192 floats covers everything.
#define ROWA        132
#define ROWW        68
#define A_STAGEF    (KC * ROWA)            // 2112
#define W_BASE      (2 * A_STAGEF)         // 4224
#define W_STAGEF    (KC * ROWW)            // 1088
#define SMEM_FLOATS 8192                   // >= 4224 + 2176 = 6400

__device__ __forceinline__ void fma2(unsigned long long& acc,
                                     unsigned long long a,
                                     unsigned long long b) {
    asm("fma.rn.f32x2 %0, %1, %2, %0;" : "+l"(acc) : "l"(a), "l"(b));
}
__device__ __forceinline__ unsigned long long packdup(float f) {
    unsigned long long d;
    const uint32_t u = __float_as_uint(f);
    asm("mov.b64 %0, {%1, %1};" : "=l"(d) : "r"(u));
    return d;
}

__global__ __launch_bounds__(NTHREADS, 4)
void router_ffma2_kernel(const float* __restrict__ tokens,
                         const int* __restrict__ t_arr,
                         const float* __restrict__ Wg,
                         const float* __restrict__ bg,
                         float* __restrict__ out)
{
    __shared__ __align__(16) float smem[SMEM_FLOATS];

    const int tid = threadIdx.x;
    const int bm  = blockIdx.x * TILE_M;
    const int tg  = tid & 15;          // token group: {4tg..4tg+3, 64+4tg..+3}
    const int eg  = tid >> 4;          // expert group: 8eg..8eg+7

    // acc[tp][e], f32x2 over token pairs; bias folded into the init so the
    // epilogue needs no bias add and no smem bias array.
    unsigned long long acc[4][8];
#pragma unroll
    for (int e = 0; e < 8; e++) {
        const unsigned long long b2 = packdup(__ldg(&bg[8 * eg + e]));
#pragma unroll
        for (int tp = 0; tp < 4; tp++) acc[tp][e] = b2;
    }

    float4 la[4], lw[2];

#define LOAD(k0)                                                               \
    {                                                                          \
        _Pragma("unroll")                                                      \
        for (int i = 0; i < 4; i++) {                                          \
            const int j = tid + NTHREADS * i;                                  \
            const int m = j >> 2, q = j & 3;                                   \
            la[i] = *reinterpret_cast<const float4*>(                          \
                tokens + (size_t)(bm + m) * ND + (k0) + 4 * q);                \
        }                                                                      \
        _Pragma("unroll")                                                      \
        for (int i = 0; i < 2; i++) {                                          \
            const int j = tid + NTHREADS * i;                                  \
            const int e = j >> 2, q = j & 3;                                   \
            lw[i] = *reinterpret_cast<const float4*>(                          \
                Wg + (size_t)e * ND + (k0) + 4 * q);                           \
        }                                                                      \
    }

// transpose scalar stores to padded rows (<=2-way bank conflicts)
#define STORE(buf)                                                             \
    {                                                                          \
        float* sa = smem + (buf) * A_STAGEF;                                   \
        float* sw = smem + W_BASE + (buf) * W_STAGEF;                          \
        _Pragma("unroll")                                                      \
        for (int i = 0; i < 4; i++) {                                          \
            const int j = tid + NTHREADS * i;                                  \
            const int m = j >> 2, q = j & 3;                                   \
            const float v[4] = {la[i].x, la[i].y, la[i].z, la[i].w};           \
            _Pragma("unroll")                                                  \
            for (int r = 0; r < 4; r++)                                        \
                sa[(4 * q + r) * ROWA + m] = v[r];                             \
        }                                                                      \
        _Pragma("unroll")                                                      \
        for (int i = 0; i < 2; i++) {                                          \
            const int j = tid + NTHREADS * i;                                  \
            const int e = j >> 2, q = j & 3;                                   \
            const float v[4] = {lw[i].x, lw[i].y, lw[i].z, lw[i].w};           \
            _Pragma("unroll")                                                  \
            for (int r = 0; r < 4; r++)                                        \
                sw[(4 * q + r) * ROWW + e] = v[r];                             \
        }                                                                      \
    }

    LOAD(0);
    STORE(0);
    __syncthreads();

    const float* saT = smem + 4 * tg;            // + buf*A_STAGEF + k*ROWA
    const float* swT = smem + W_BASE + 8 * eg;   // + buf*W_STAGEF + k*ROWW

    for (int ch = 0; ch < NCHUNK; ch++) {
        const int buf = ch & 1;
        if (ch + 1 < NCHUNK) LOAD((ch + 1) * KC);

        const float* sa = saT + buf * A_STAGEF;
        const float* sw = swT + buf * W_STAGEF;

        // ---- explicit 2-deep software pipeline over k ----
        ulonglong2 A0c = *reinterpret_cast<const ulonglong2*>(sa);
        ulonglong2 A1c = *reinterpret_cast<const ulonglong2*>(sa + 64);
        float4     w0c = *reinterpret_cast<const float4*>(sw);
        float4     w1c = *reinterpret_cast<const float4*>(sw + 4);

#pragma unroll
        for (int k = 0; k < KC; k++) {
            ulonglong2 A0n, A1n;
            float4 w0n, w1n;
            if (k + 1 < KC) {
                A0n = *reinterpret_cast<const ulonglong2*>(sa + (k + 1) * ROWA);
                A1n = *reinterpret_cast<const ulonglong2*>(sa + (k + 1) * ROWA + 64);
                w0n = *reinterpret_cast<const float4*>(sw + (k + 1) * ROWW);
                w1n = *reinterpret_cast<const float4*>(sw + (k + 1) * ROWW + 4);
            }

            const unsigned long long a64[4] = {A0c.x, A0c.y, A1c.x, A1c.y};
            const unsigned long long wd[8] = {
                packdup(w0c.x), packdup(w0c.y), packdup(w0c.z), packdup(w0c.w),
                packdup(w1c.x), packdup(w1c.y), packdup(w1c.z), packdup(w1c.w)};
#pragma unroll
            for (int tp = 0; tp < 4; tp++)
#pragma unroll
                for (int e = 0; e < 8; e++) fma2(acc[tp][e], a64[tp], wd[e]);

            if (k + 1 < KC) { A0c = A0n; A1c = A1n; w0c = w0n; w1c = w1n; }
        }

        if (ch + 1 < NCHUNK) STORE(buf ^ 1);   // disjoint buffer: safe pre-sync
        __syncthreads();
    }

    // ---- scatter acc -> swizzled logits overlay ----
    float* slog = smem;   // [128][64], col e ^ (m&31)
#pragma unroll
    for (int tp = 0; tp < 4; tp++) {
        const int m0 = ((tp & 1) ? 4 * tg + 2 : 4 * tg) + ((tp & 2) ? 64 : 0);
        const int m1 = m0 + 1;
#pragma unroll
        for (int e = 0; e < 8; e++) {
            const int ex = 8 * eg + e;
            slog[m0 * 64 + (ex ^ (m0 & 31))] =
                __uint_as_float((uint32_t)acc[tp][e]);
            slog[m1 * 64 + (ex ^ (m1 & 31))] =
                __uint_as_float((uint32_t)(acc[tp][e] >> 32));
        }
    }
    __syncthreads();

    // ---- per-token epilogue (identical math to the passing kernels;
    //      bias already inside the logits) ----
    {
        const int m = tid;
        const int gtok = bm + m;
        const float cap = 0.5f + 1.1f * ((float)t_arr[gtok >> 12] / 1000.0f);
        const int msw = m & 31;
        const float* row = slog + m * 64;

        float p[NE];
#pragma unroll
        for (int e = 0; e < NE; e++) p[e] = row[e ^ msw];

        float mx = -3.402823466e38f;
#pragma unroll 8
        for (int e = 0; e < NE; e++) mx = fmaxf(mx, p[e]);
        float s = 0.0f;
#pragma unroll 4
        for (int e = 0; e < NE; e++) { const float v = expf(p[e] - mx); s += v; p[e] = v; }
        const float inv = 1.0f / s;

        float summin = 0.0f, sumex = 0.0f;
#pragma unroll 8
        for (int e = 0; e < NE; e++) {
            const float q = 0.85f * (p[e] * inv) + (0.15f / 64.0f);
            p[e] = q;
            const float cc = fminf(q, cap);
            summin += cc;
            sumex += q - cc;
        }
        const float hs = fmaxf(64.0f * cap - summin, 1e-8f);
        const float scale = sumex / hs;

        float v1 = -1.0f, v2 = -1.0f;
        int i1 = 0, i2 = 0;
#pragma unroll 8
        for (int e = 0; e < NE; e++) {
            const float cc = fminf(p[e], cap);
            const float f = cc + scale * (cap - cc);
            if (f > v1)      { v2 = v1; i2 = i1; v1 = f; i1 = e; }
            else if (f > v2) { v2 = f; i2 = e; }
        }

        float* orow = out + (size_t)gtok * NE;
        const float4 z = make_float4(0.f, 0.f, 0.f, 0.f);
#pragma unroll
        for (int u = 0; u < 16; u++) reinterpret_cast<float4*>(orow)[u] = z;
        orow[i1] = v1;
        orow[i2] = v2;
    }
}

extern "C" void kernel_launch(void* const* d_in, const int* in_sizes, int n_in,
                              void* d_out, int out_size)
{
    const float* tokens = (const float*)d_in[0];   // (16, 4096, 1024) f32
    const int*   t_arr  = (const int*)d_in[1];     // (16,) i32
    const float* Wg     = (const float*)d_in[2];   // (64, 1024) f32
    const float* bg     = (const float*)d_in[3];   // (64,) f32
    float*       out    = (float*)d_out;           // (16, 4096, 64) f32

    router_ffma2_kernel<<<NTOK / TILE_M, NTHREADS>>>(tokens, t_arr, Wg, bg, out);
}